// round 11
// baseline (speedup 1.0000x reference)
#include <cuda_runtime.h>
#include <cstdint>

#define PS 5
#define NT 2
#define PH 536
#define PW 536
#define OH 532
#define OW 532
#define PDIM 75
#define HW (PH*PW)

#define TX 32
#define TXH (TX+4)            // 36
#define CHUNK (TXH*PDIM)      // 2700 floats per patch row window
#define CSTRIDE 2700          // 10800 B, 16B-aligned
#define WSTR 40               // weight slot stride (160 B)
#define RING 20               // row-ring slots
#define RPS 8                 // output rows per stage
#define NB 4                  // stage mbarriers
#define TPB 256
#define NX 17
#define NSTRIPS 4
#define SROWS 133             // 4*133 = 532
#define VBYTES 10800          // CHUNK*4
#define WBYTES 144            // TXH*4
#define NCTA (NX*NSTRIPS*NT)  // 136

// smem layout (floats)
#define SVAL_OFF   0
#define SWT_OFF    (RING*CSTRIDE)             // 54000
#define SMEANS_OFF (SWT_OFF + RING*WSTR)      // 54800
#define MBAR_OFF   (SMEANS_OFF + 8)           // 54808 (byte 219232, 16B aligned)
#define SMEM_FLOATS (MBAR_OFF + 2*NB)
#define SMEM_BYTES  (SMEM_FLOATS*4)           // 219,264 B

__device__ float    g_part[NCTA * 6];
__device__ int      g_flags[NCTA];
__device__ unsigned g_c2;   // departure counter (last CTA resets state)

// ---------------- PTX helpers ------------------------------------------------
__device__ __forceinline__ uint32_t smem_u32(const void* p) {
    return (uint32_t)__cvta_generic_to_shared(p);
}
__device__ __forceinline__ void mbar_init(uint32_t a, uint32_t cnt) {
    asm volatile("mbarrier.init.shared.b64 [%0], %1;" :: "r"(a), "r"(cnt) : "memory");
}
__device__ __forceinline__ void mbar_expect(uint32_t a, uint32_t bytes) {
    asm volatile("mbarrier.arrive.expect_tx.shared.b64 _, [%0], %1;"
                 :: "r"(a), "r"(bytes) : "memory");
}
__device__ __forceinline__ void mbar_wait(uint32_t a, uint32_t parity) {
    asm volatile(
        "{\n\t.reg .pred P;\n\t"
        "WL_%=:\n\t"
        "mbarrier.try_wait.parity.shared.b64 P, [%0], %1, 0x989680;\n\t"
        "@P bra.uni WD_%=;\n\t"
        "bra.uni WL_%=;\n\t"
        "WD_%=:\n\t}"
        :: "r"(a), "r"(parity) : "memory");
}
__device__ __forceinline__ void bulk_g2s(uint32_t dst, const void* src,
                                         uint32_t bytes, uint32_t mbar) {
    asm volatile(
        "cp.async.bulk.shared::cta.global.mbarrier::complete_tx::bytes "
        "[%0], [%1], %2, [%3];"
        :: "r"(dst), "l"(src), "r"(bytes), "r"(mbar) : "memory");
}

// ---------------- fused persistent kernel ------------------------------------
extern __shared__ float smem[];

__global__ void __launch_bounds__(TPB, 1)
fold_kernel(const float* __restrict__ noisy,
            const float* __restrict__ deno,
            const float* __restrict__ pwts,
            float* __restrict__ out) {
    const int t     = blockIdx.z;
    const int strip = blockIdx.y;
    const int bx    = blockIdx.x;
    const int cid   = bx + NX * (strip + NSTRIPS * t);

    const int x0    = bx * TX;
    const int xbase = min(x0, PW - TXH);   // all multiples of 4 -> 16B aligned rows
    const int xoff  = x0 - xbase;

    const int ys = strip * SROWS;
    const int ye = min(ys + SROWS, OH);
    const int nstages = (ye - ys + RPS - 1) / RPS;   // 17

    const float* dptr = deno + (size_t)t * HW * PDIM;
    const float* wptr = pwts + (size_t)t * HW;

    float* sval   = smem + SVAL_OFF;
    float* swt    = smem + SWT_OFF;
    float* smeans = smem + SMEANS_OFF;
    const uint32_t mb0   = smem_u32(smem + MBAR_OFF);
    const uint32_t svalA = smem_u32(sval);
    const uint32_t swtA  = smem_u32(swt);

    const int tid = threadIdx.x;
    const int tx  = tid & 31;
    const int wid = tid >> 5;          // output row within stage
    const int Xo  = x0 + tx;

    if (tid < NB) mbar_init(mb0 + tid * 8, 1);
    __syncthreads();

    // -------- deep prologue: fetch stages 0 AND 1 (rows [ys, ys+20)) --------
    // keeps the DMA engine busy through the means + handshake phase.
    if (tid == 0) {
        asm volatile("fence.proxy.async.shared::cta;" ::: "memory");
        // stage 0: rows [ys, ys+12)
        {
            const int r0 = ys, r1 = min(ys + RPS + 4, ye + 4);
            mbar_expect(mb0, (uint32_t)((r1 - r0) * (VBYTES + WBYTES)));
            for (int r = r0; r < r1; r++) {
                const int slot  = r % RING;
                const int rbase = r * PW + xbase;
                bulk_g2s(svalA + (uint32_t)(slot * CSTRIDE) * 4,
                         dptr + (size_t)rbase * PDIM, VBYTES, mb0);
                bulk_g2s(swtA + (uint32_t)(slot * WSTR) * 4,
                         wptr + rbase, WBYTES, mb0);
            }
        }
        // stage 1: rows [ys+12, ys+20)
        if (nstages > 1) {
            const int r0 = ys + RPS + 4, r1 = min(ys + 2 * RPS + 4, ye + 4);
            mbar_expect(mb0 + 8, (uint32_t)((r1 - r0) * (VBYTES + WBYTES)));
            for (int r = r0; r < r1; r++) {
                const int slot  = r % RING;
                const int rbase = r * PW + xbase;
                bulk_g2s(svalA + (uint32_t)(slot * CSTRIDE) * 4,
                         dptr + (size_t)rbase * PDIM, VBYTES, mb0 + 8);
                bulk_g2s(swtA + (uint32_t)(slot * WSTR) * 4,
                         wptr + rbase, WBYTES, mb0 + 8);
            }
        }
    }

    // -------- means partials: warps 0-5, one noisy plane each (overlaps DMA) -
    {
        const int plane = OH * OW;
        const int n4 = plane / 4;                       // 70756
        const int s0 = (int)(((long long)cid * n4) / NCTA);
        const int s1 = (int)(((long long)(cid + 1) * n4) / NCTA);
        const int lane = tid & 31;
        if (wid < 6) {
            const float4* p = (const float4*)(noisy + (size_t)wid * plane);
            float s = 0.f;
            for (int i = s0 + lane; i < s1; i += 32) {
                float4 v = p[i];
                s += (v.x + v.y) + (v.z + v.w);
            }
            #pragma unroll
            for (int o = 16; o; o >>= 1) s += __shfl_down_sync(0xffffffffu, s, o);
            if (lane == 0) g_part[cid * 6 + wid] = s;
        }
    }
    __syncthreads();

    // -------- publish + low-contention flag barrier --------
    if (tid == 0) {
        __threadfence();
        *((volatile int*)&g_flags[cid]) = 1;
    }
    if (wid == 0) {   // warp 0 polls all flags with plain L2 reads
        const int lane = tid & 31;
        volatile int* vf = (volatile int*)g_flags;
        for (;;) {
            int mine = 1;
            #pragma unroll
            for (int k = 0; k < 5; k++) {
                int idx = lane + 32 * k;
                if (idx < NCTA) mine &= vf[idx];
            }
            if (__all_sync(0xffffffffu, mine)) break;
        }
        __threadfence();   // acquire: order g_part reads after flag observation
    }
    __syncthreads();

    // -------- final means for this t (deterministic fixed-order reduce) ------
    if (tid < 96) {
        const int c = tid >> 5, lane = tid & 31;
        float s = 0.f;
        for (int k = lane; k < NCTA; k += 32) s += g_part[k * 6 + t * 3 + c];
        #pragma unroll
        for (int o = 16; o; o >>= 1) s += __shfl_down_sync(0xffffffffu, s, o);
        if (lane == 0) smeans[c] = s * (1.0f / (float)(OH * OW));
    }
    __syncthreads();

    const float m0 = smeans[0];
    const float m1 = smeans[1];
    const float m2 = smeans[2];

    // departure: last CTA resets flags + counter for the next graph replay
    if (tid == 0) {
        unsigned r2 = atomicAdd(&g_c2, 1u);
        if (r2 == (unsigned)(NCTA - 1)) {
            for (int k = 0; k < NCTA; k++) g_flags[k] = 0;
            atomicExch(&g_c2, 0u);
        }
    }

    const size_t plane = (size_t)OH * OW;

    // -------- stage loop: 8 output rows/stage; stages 0,1 already in flight --
    for (int s = 0; s < nstages; s++) {
        if (tid == 0 && s >= 1 && s + 1 < nstages) {
            const int r0 = ys + RPS * s + RPS + 4;
            const int r1 = min(ys + RPS * (s + 1) + RPS + 4, ye + 4);
            const uint32_t mb = mb0 + ((s + 1) % NB) * 8;
            mbar_expect(mb, (uint32_t)((r1 - r0) * (VBYTES + WBYTES)));
            for (int r = r0; r < r1; r++) {
                const int slot  = r % RING;
                const int rbase = r * PW + xbase;
                bulk_g2s(svalA + (uint32_t)(slot * CSTRIDE) * 4,
                         dptr + (size_t)rbase * PDIM, VBYTES, mb);
                bulk_g2s(swtA + (uint32_t)(slot * WSTR) * 4,
                         wptr + rbase, WBYTES, mb);
            }
        }

        mbar_wait(mb0 + (s % NB) * 8, (uint32_t)((s >> 2) & 1));

        const int Yo = ys + RPS * s + wid;
        if (Yo < ye && Xo < OW) {
            const int sb = (ys + RPS * s) % RING;

            float a0 = 0.f, a1 = 0.f, a2 = 0.f, cnt = 0.f;
            #pragma unroll
            for (int i = 0; i < PS; i++) {
                int sl = sb + wid + 4 - i;
                if (sl >= RING) sl -= RING;
                const float* vrow = sval + sl * CSTRIDE;
                const float* wrow = swt + sl * WSTR;
                #pragma unroll
                for (int j = 0; j < PS; j++) {
                    const int lx = xoff + tx + 4 - j;
                    const float w = wrow[lx];
                    const float* v = vrow + lx * PDIM;  // stride 75: conflict-free
                    const int sidx = i * PS + j;
                    cnt += w;
                    a0 = fmaf(v[sidx],      w, a0);
                    a1 = fmaf(v[25 + sidx], w, a1);
                    a2 = fmaf(v[50 + sidx], w, a2);
                }
            }

            const float inv = 0.5f / cnt;
            size_t o = (size_t)t * 3 * plane + (size_t)Yo * OW + Xo;
            out[o]             = a0 * inv + m0;
            out[o + plane]     = a1 * inv + m1;
            out[o + 2 * plane] = a2 * inv + m2;
        }
        __syncthreads();   // stage boundary: protects ring-slot reuse
    }
}

// ---------------- launch ------------------------------------------------------
extern "C" void kernel_launch(void* const* d_in, const int* in_sizes, int n_in,
                              void* d_out, int out_size) {
    const float* noisy = (const float*)d_in[0];
    const float* deno  = (const float*)d_in[1];
    const float* pwts  = (const float*)d_in[2];
    float* out = (float*)d_out;

    cudaFuncSetAttribute(fold_kernel,
                         cudaFuncAttributeMaxDynamicSharedMemorySize,
                         SMEM_BYTES);

    dim3 grid(NX, NSTRIPS, NT);   // 17 x 4 x 2 = 136 CTAs, one wave
    fold_kernel<<<grid, TPB, SMEM_BYTES>>>(noisy, deno, pwts, out);
}

// round 12
// speedup vs baseline: 1.1053x; 1.1053x over previous
#include <cuda_runtime.h>
#include <cstdint>

#define PS 5
#define NT 2
#define PH 536
#define PW 536
#define OH 532
#define OW 532
#define PDIM 75
#define HW (PH*PW)

#define TX 32
#define TXH (TX+4)            // 36
#define CHUNK (TXH*PDIM)      // 2700 floats per patch row window
#define CSTRIDE 2700          // 10800 B, 16B-aligned
#define WSTR 40               // weight slot stride (160 B)
#define RING 20               // row-ring slots
#define RPS 8                 // output rows per stage
#define NB 4                  // stage mbarriers
#define TPB 256
#define NX 17
#define NSTRIPS 4
#define SROWS 133             // 4*133 = 532
#define VBYTES 10800          // CHUNK*4
#define WBYTES 144            // TXH*4

// smem layout (floats)
#define SVAL_OFF   0
#define SWT_OFF    (RING*CSTRIDE)             // 54000
#define SMEANS_OFF (SWT_OFF + RING*WSTR)      // 54800
#define MBAR_OFF   (SMEANS_OFF + 8)           // 54808 (byte 219232, 16B aligned)
#define SMEM_FLOATS (MBAR_OFF + 2*NB)
#define SMEM_BYTES  (SMEM_FLOATS*4)           // 219,264 B

#define MEANS_CHUNKS 24       // 6*24 = 144 blocks, one clean wave

__device__ float g_part[6 * MEANS_CHUNKS];

// ---------------- PTX helpers ------------------------------------------------
__device__ __forceinline__ uint32_t smem_u32(const void* p) {
    return (uint32_t)__cvta_generic_to_shared(p);
}
__device__ __forceinline__ void mbar_init(uint32_t a, uint32_t cnt) {
    asm volatile("mbarrier.init.shared.b64 [%0], %1;" :: "r"(a), "r"(cnt) : "memory");
}
__device__ __forceinline__ void mbar_expect(uint32_t a, uint32_t bytes) {
    asm volatile("mbarrier.arrive.expect_tx.shared.b64 _, [%0], %1;"
                 :: "r"(a), "r"(bytes) : "memory");
}
__device__ __forceinline__ void mbar_wait(uint32_t a, uint32_t parity) {
    asm volatile(
        "{\n\t.reg .pred P;\n\t"
        "WL_%=:\n\t"
        "mbarrier.try_wait.parity.shared.b64 P, [%0], %1, 0x989680;\n\t"
        "@P bra.uni WD_%=;\n\t"
        "bra.uni WL_%=;\n\t"
        "WD_%=:\n\t}"
        :: "r"(a), "r"(parity) : "memory");
}
__device__ __forceinline__ void bulk_g2s(uint32_t dst, const void* src,
                                         uint32_t bytes, uint32_t mbar) {
    asm volatile(
        "cp.async.bulk.shared::cta.global.mbarrier::complete_tx::bytes "
        "[%0], [%1], %2, [%3];"
        :: "r"(dst), "l"(src), "r"(bytes), "r"(mbar) : "memory");
}

// ---------------- means: partial sums ----------------------------------------
__global__ void __launch_bounds__(512)
means_partial_kernel(const float* __restrict__ noisy) {
    int tc    = blockIdx.x;          // 0..5
    int chunk = blockIdx.y;          // 0..MEANS_CHUNKS-1
    const int plane = OH * OW;
    const float4* p = (const float4*)(noisy + (size_t)tc * plane);
    const int n4 = plane / 4;        // 70756
    float s = 0.f;
    #pragma unroll 8
    for (int i = chunk * 512 + threadIdx.x; i < n4; i += MEANS_CHUNKS * 512) {
        float4 v = p[i];
        s += (v.x + v.y) + (v.z + v.w);
    }
    __shared__ float red[32];
    #pragma unroll
    for (int o = 16; o; o >>= 1) s += __shfl_down_sync(0xffffffffu, s, o);
    if ((threadIdx.x & 31) == 0) red[threadIdx.x >> 5] = s;
    __syncthreads();
    if (threadIdx.x < 32) {
        float v = (threadIdx.x < 16) ? red[threadIdx.x] : 0.f;
        #pragma unroll
        for (int o = 16; o; o >>= 1) v += __shfl_down_sync(0xffffffffu, v, o);
        if (threadIdx.x == 0) g_part[tc * MEANS_CHUNKS + chunk] = v;
    }
}

// ---------------- persistent fold kernel --------------------------------------
extern __shared__ float smem[];

__global__ void __launch_bounds__(TPB, 1)
fold_kernel(const float* __restrict__ deno,
            const float* __restrict__ pwts,
            float* __restrict__ out) {
    const int t     = blockIdx.z;
    const int strip = blockIdx.y;
    const int x0    = blockIdx.x * TX;
    const int xbase = min(x0, PW - TXH);   // all multiples of 4 -> 16B aligned
    const int xoff  = x0 - xbase;

    const int ys = strip * SROWS;
    const int ye = min(ys + SROWS, OH);
    const int nstages = (ye - ys + RPS - 1) / RPS;   // 17

    const float* dptr = deno + (size_t)t * HW * PDIM;
    const float* wptr = pwts + (size_t)t * HW;

    float* sval   = smem + SVAL_OFF;
    float* swt    = smem + SWT_OFF;
    float* smeans = smem + SMEANS_OFF;
    const uint32_t mb0   = smem_u32(smem + MBAR_OFF);
    const uint32_t svalA = smem_u32(sval);
    const uint32_t swtA  = smem_u32(swt);

    const int tid = threadIdx.x;
    const int tx  = tid & 31;
    const int wid = tid >> 5;          // output row within stage
    const int Xo  = x0 + tx;

    if (tid < NB) mbar_init(mb0 + tid * 8, 1);
    __syncthreads();

    // -------- deep prologue: stage 0 (rows [ys,ys+12)) + stage 1 ([+12,+20)) -
    if (tid == 0) {
        asm volatile("fence.proxy.async.shared::cta;" ::: "memory");
        {
            const int r0 = ys, r1 = min(ys + RPS + 4, ye + 4);
            mbar_expect(mb0, (uint32_t)((r1 - r0) * (VBYTES + WBYTES)));
            for (int r = r0; r < r1; r++) {
                const int slot  = r % RING;
                const int rbase = r * PW + xbase;
                bulk_g2s(svalA + (uint32_t)(slot * CSTRIDE) * 4,
                         dptr + (size_t)rbase * PDIM, VBYTES, mb0);
                bulk_g2s(swtA + (uint32_t)(slot * WSTR) * 4,
                         wptr + rbase, WBYTES, mb0);
            }
        }
        if (nstages > 1) {
            const int r0 = ys + RPS + 4, r1 = min(ys + 2 * RPS + 4, ye + 4);
            mbar_expect(mb0 + 8, (uint32_t)((r1 - r0) * (VBYTES + WBYTES)));
            for (int r = r0; r < r1; r++) {
                const int slot  = r % RING;
                const int rbase = r * PW + xbase;
                bulk_g2s(svalA + (uint32_t)(slot * CSTRIDE) * 4,
                         dptr + (size_t)rbase * PDIM, VBYTES, mb0 + 8);
                bulk_g2s(swtA + (uint32_t)(slot * WSTR) * 4,
                         wptr + rbase, WBYTES, mb0 + 8);
            }
        }
    }

    // -------- final means from g_part (stream-ordered: no grid sync needed) --
    if (tid < 192) {
        const int c = tid >> 5, lane = tid & 31;   // c = 0..5
        float s = (lane < MEANS_CHUNKS) ? g_part[c * MEANS_CHUNKS + lane] : 0.f;
        #pragma unroll
        for (int o = 16; o; o >>= 1) s += __shfl_down_sync(0xffffffffu, s, o);
        if (lane == 0) smeans[c] = s * (1.0f / (float)(OH * OW));
    }
    __syncthreads();

    const float m0 = smeans[t * 3 + 0];
    const float m1 = smeans[t * 3 + 1];
    const float m2 = smeans[t * 3 + 2];
    const size_t plane = (size_t)OH * OW;

    // -------- stage loop: 8 rows/stage; stages 0,1 already in flight ---------
    for (int s = 0; s < nstages; s++) {
        if (tid == 0 && s >= 1 && s + 1 < nstages) {
            const int r0 = ys + RPS * s + RPS + 4;
            const int r1 = min(ys + RPS * (s + 1) + RPS + 4, ye + 4);
            const uint32_t mb = mb0 + ((s + 1) % NB) * 8;
            mbar_expect(mb, (uint32_t)((r1 - r0) * (VBYTES + WBYTES)));
            for (int r = r0; r < r1; r++) {
                const int slot  = r % RING;
                const int rbase = r * PW + xbase;
                bulk_g2s(svalA + (uint32_t)(slot * CSTRIDE) * 4,
                         dptr + (size_t)rbase * PDIM, VBYTES, mb);
                bulk_g2s(swtA + (uint32_t)(slot * WSTR) * 4,
                         wptr + rbase, WBYTES, mb);
            }
        }

        mbar_wait(mb0 + (s % NB) * 8, (uint32_t)((s >> 2) & 1));

        const int Yo = ys + RPS * s + wid;
        if (Yo < ye && Xo < OW) {
            const int sb = (ys + RPS * s) % RING;

            float a0 = 0.f, a1 = 0.f, a2 = 0.f, cnt = 0.f;
            #pragma unroll
            for (int i = 0; i < PS; i++) {
                int sl = sb + wid + 4 - i;
                if (sl >= RING) sl -= RING;
                const float* vrow = sval + sl * CSTRIDE;
                const float* wrow = swt + sl * WSTR;
                #pragma unroll
                for (int j = 0; j < PS; j++) {
                    const int lx = xoff + tx + 4 - j;
                    const float w = wrow[lx];
                    const float* v = vrow + lx * PDIM;  // stride 75: conflict-free
                    const int sidx = i * PS + j;
                    cnt += w;
                    a0 = fmaf(v[sidx],      w, a0);
                    a1 = fmaf(v[25 + sidx], w, a1);
                    a2 = fmaf(v[50 + sidx], w, a2);
                }
            }

            const float inv = 0.5f / cnt;
            size_t o = (size_t)t * 3 * plane + (size_t)Yo * OW + Xo;
            out[o]             = a0 * inv + m0;
            out[o + plane]     = a1 * inv + m1;
            out[o + 2 * plane] = a2 * inv + m2;
        }
        __syncthreads();   // stage boundary: protects ring-slot reuse
    }
}

// ---------------- launch ------------------------------------------------------
extern "C" void kernel_launch(void* const* d_in, const int* in_sizes, int n_in,
                              void* d_out, int out_size) {
    const float* noisy = (const float*)d_in[0];
    const float* deno  = (const float*)d_in[1];
    const float* pwts  = (const float*)d_in[2];
    float* out = (float*)d_out;

    cudaFuncSetAttribute(fold_kernel,
                         cudaFuncAttributeMaxDynamicSharedMemorySize,
                         SMEM_BYTES);

    dim3 mg(6, MEANS_CHUNKS);
    means_partial_kernel<<<mg, 512>>>(noisy);

    dim3 grid(NX, NSTRIPS, NT);   // 17 x 4 x 2 = 136 CTAs, one wave
    fold_kernel<<<grid, TPB, SMEM_BYTES>>>(deno, pwts, out);
}

// round 13
// speedup vs baseline: 1.1546x; 1.0447x over previous
#include <cuda_runtime.h>
#include <cstdint>

#define PS 5
#define NT 2
#define PH 536
#define PW 536
#define OH 532
#define OW 532
#define PDIM 75
#define HW (PH*PW)

#define TX 32
#define TXH (TX+4)            // 36
#define CHUNK (TXH*PDIM)      // 2700 floats per patch row window
#define CSTRIDE 2700          // 10800 B, 16B-aligned
#define WSTR 40               // weight slot stride (160 B)
#define RING 20               // row-ring slots
#define RPS 8                 // output rows per stage
#define NB 4                  // stage mbarriers
#define TPB 256
#define NX 17
#define NSTRIPS 4
#define SROWS 133             // 4*133 = 532
#define VBYTES 10800          // CHUNK*4
#define WBYTES 144            // TXH*4

// smem layout (floats)
#define SVAL_OFF   0
#define SWT_OFF    (RING*CSTRIDE)             // 54000
#define SMEANS_OFF (SWT_OFF + RING*WSTR)      // 54800
#define MBAR_OFF   (SMEANS_OFF + 8)           // 54808 (byte 219232, 16B aligned)
#define SMEM_FLOATS (MBAR_OFF + 2*NB)
#define SMEM_BYTES  (SMEM_FLOATS*4)           // 219,264 B

#define MEANS_CHUNKS 24       // 6*24 = 144 blocks, one clean wave

__device__ float g_part[6 * MEANS_CHUNKS];

// ---------------- PTX helpers ------------------------------------------------
__device__ __forceinline__ uint32_t smem_u32(const void* p) {
    return (uint32_t)__cvta_generic_to_shared(p);
}
__device__ __forceinline__ void mbar_init(uint32_t a, uint32_t cnt) {
    asm volatile("mbarrier.init.shared.b64 [%0], %1;" :: "r"(a), "r"(cnt) : "memory");
}
__device__ __forceinline__ void mbar_expect(uint32_t a, uint32_t bytes) {
    asm volatile("mbarrier.arrive.expect_tx.shared.b64 _, [%0], %1;"
                 :: "r"(a), "r"(bytes) : "memory");
}
__device__ __forceinline__ void mbar_wait(uint32_t a, uint32_t parity) {
    asm volatile(
        "{\n\t.reg .pred P;\n\t"
        "WL_%=:\n\t"
        "mbarrier.try_wait.parity.shared.b64 P, [%0], %1, 0x989680;\n\t"
        "@P bra.uni WD_%=;\n\t"
        "bra.uni WL_%=;\n\t"
        "WD_%=:\n\t}"
        :: "r"(a), "r"(parity) : "memory");
}
__device__ __forceinline__ void bulk_g2s(uint32_t dst, const void* src,
                                         uint32_t bytes, uint32_t mbar) {
    asm volatile(
        "cp.async.bulk.shared::cta.global.mbarrier::complete_tx::bytes "
        "[%0], [%1], %2, [%3];"
        :: "r"(dst), "l"(src), "r"(bytes), "r"(mbar) : "memory");
}
__device__ __forceinline__ void grid_dep_wait() {
    asm volatile("griddepcontrol.wait;" ::: "memory");
}

// ---------------- means: partial sums ----------------------------------------
__global__ void __launch_bounds__(512)
means_partial_kernel(const float* __restrict__ noisy) {
    int tc    = blockIdx.x;          // 0..5
    int chunk = blockIdx.y;          // 0..MEANS_CHUNKS-1
    const int plane = OH * OW;
    const float4* p = (const float4*)(noisy + (size_t)tc * plane);
    const int n4 = plane / 4;        // 70756
    float s = 0.f;
    #pragma unroll 8
    for (int i = chunk * 512 + threadIdx.x; i < n4; i += MEANS_CHUNKS * 512) {
        float4 v = p[i];
        s += (v.x + v.y) + (v.z + v.w);
    }
    __shared__ float red[32];
    #pragma unroll
    for (int o = 16; o; o >>= 1) s += __shfl_down_sync(0xffffffffu, s, o);
    if ((threadIdx.x & 31) == 0) red[threadIdx.x >> 5] = s;
    __syncthreads();
    if (threadIdx.x < 32) {
        float v = (threadIdx.x < 16) ? red[threadIdx.x] : 0.f;
        #pragma unroll
        for (int o = 16; o; o >>= 1) v += __shfl_down_sync(0xffffffffu, v, o);
        if (threadIdx.x == 0) g_part[tc * MEANS_CHUNKS + chunk] = v;
    }
}

// ---------------- persistent fold kernel --------------------------------------
extern __shared__ float smem[];

__global__ void __launch_bounds__(TPB, 1)
fold_kernel(const float* __restrict__ deno,
            const float* __restrict__ pwts,
            float* __restrict__ out) {
    const int t     = blockIdx.z;
    const int strip = blockIdx.y;
    const int x0    = blockIdx.x * TX;
    const int xbase = min(x0, PW - TXH);   // all multiples of 4 -> 16B aligned
    const int xoff  = x0 - xbase;

    const int ys = strip * SROWS;
    const int ye = min(ys + SROWS, OH);
    const int nstages = (ye - ys + RPS - 1) / RPS;   // 17

    const float* dptr = deno + (size_t)t * HW * PDIM;
    const float* wptr = pwts + (size_t)t * HW;

    float* sval   = smem + SVAL_OFF;
    float* swt    = smem + SWT_OFF;
    float* smeans = smem + SMEANS_OFF;
    const uint32_t mb0   = smem_u32(smem + MBAR_OFF);
    const uint32_t svalA = smem_u32(sval);
    const uint32_t swtA  = smem_u32(swt);

    const int tid = threadIdx.x;
    const int tx  = tid & 31;
    const int wid = tid >> 5;          // output row within stage
    const int Xo  = x0 + tx;

    if (tid < NB) mbar_init(mb0 + tid * 8, 1);
    __syncthreads();

    // -------- deep prologue: stage 0 (rows [ys,ys+12)) + stage 1 ([+12,+20)) -
    // Issued BEFORE the PDL dependency wait: TMA streams while means_partial
    // (still running under programmatic launch) finishes.
    if (tid == 0) {
        asm volatile("fence.proxy.async.shared::cta;" ::: "memory");
        {
            const int r0 = ys, r1 = min(ys + RPS + 4, ye + 4);
            mbar_expect(mb0, (uint32_t)((r1 - r0) * (VBYTES + WBYTES)));
            for (int r = r0; r < r1; r++) {
                const int slot  = r % RING;
                const int rbase = r * PW + xbase;
                bulk_g2s(svalA + (uint32_t)(slot * CSTRIDE) * 4,
                         dptr + (size_t)rbase * PDIM, VBYTES, mb0);
                bulk_g2s(swtA + (uint32_t)(slot * WSTR) * 4,
                         wptr + rbase, WBYTES, mb0);
            }
        }
        if (nstages > 1) {
            const int r0 = ys + RPS + 4, r1 = min(ys + 2 * RPS + 4, ye + 4);
            mbar_expect(mb0 + 8, (uint32_t)((r1 - r0) * (VBYTES + WBYTES)));
            for (int r = r0; r < r1; r++) {
                const int slot  = r % RING;
                const int rbase = r * PW + xbase;
                bulk_g2s(svalA + (uint32_t)(slot * CSTRIDE) * 4,
                         dptr + (size_t)rbase * PDIM, VBYTES, mb0 + 8);
                bulk_g2s(swtA + (uint32_t)(slot * WSTR) * 4,
                         wptr + rbase, WBYTES, mb0 + 8);
            }
        }
    }

    float m0 = 0.f, m1 = 0.f, m2 = 0.f;   // set at s==0, used from first store on
    const size_t plane = (size_t)OH * OW;

    // -------- stage loop: 8 rows/stage; stages 0,1 already in flight ---------
    for (int s = 0; s < nstages; s++) {
        if (tid == 0 && s >= 1 && s + 1 < nstages) {
            const int r0 = ys + RPS * s + RPS + 4;
            const int r1 = min(ys + RPS * (s + 1) + RPS + 4, ye + 4);
            const uint32_t mb = mb0 + ((s + 1) % NB) * 8;
            mbar_expect(mb, (uint32_t)((r1 - r0) * (VBYTES + WBYTES)));
            for (int r = r0; r < r1; r++) {
                const int slot  = r % RING;
                const int rbase = r * PW + xbase;
                bulk_g2s(svalA + (uint32_t)(slot * CSTRIDE) * 4,
                         dptr + (size_t)rbase * PDIM, VBYTES, mb);
                bulk_g2s(swtA + (uint32_t)(slot * WSTR) * 4,
                         wptr + rbase, WBYTES, mb);
            }
        }

        mbar_wait(mb0 + (s % NB) * 8, (uint32_t)((s >> 2) & 1));

        const int Yo = ys + RPS * s + wid;
        const bool active = (Yo < ye) && (Xo < OW);

        float a0 = 0.f, a1 = 0.f, a2 = 0.f, cnt = 0.f;
        if (active) {
            const int sb = (ys + RPS * s) % RING;
            #pragma unroll
            for (int i = 0; i < PS; i++) {
                int sl = sb + wid + 4 - i;
                if (sl >= RING) sl -= RING;
                const float* vrow = sval + sl * CSTRIDE;
                const float* wrow = swt + sl * WSTR;
                #pragma unroll
                for (int j = 0; j < PS; j++) {
                    const int lx = xoff + tx + 4 - j;
                    const float w = wrow[lx];
                    const float* v = vrow + lx * PDIM;  // stride 75: conflict-free
                    const int sidx = i * PS + j;
                    cnt += w;
                    a0 = fmaf(v[sidx],      w, a0);
                    a1 = fmaf(v[25 + sidx], w, a1);
                    a2 = fmaf(v[50 + sidx], w, a2);
                }
            }
        }

        if (s == 0) {
            // Deferred PDL dependency: means_partial has had the whole
            // prologue + stage-0 gather to finish.  No-op if serialized.
            grid_dep_wait();
            if (tid < 192) {
                const int c = tid >> 5, lane = tid & 31;   // c = 0..5
                float v = (lane < MEANS_CHUNKS) ? g_part[c * MEANS_CHUNKS + lane] : 0.f;
                #pragma unroll
                for (int o = 16; o; o >>= 1) v += __shfl_down_sync(0xffffffffu, v, o);
                if (lane == 0) smeans[c] = v * (1.0f / (float)(OH * OW));
            }
            __syncthreads();
            m0 = smeans[t * 3 + 0];
            m1 = smeans[t * 3 + 1];
            m2 = smeans[t * 3 + 2];
        }

        if (active) {
            const float inv = 0.5f / cnt;
            size_t o = (size_t)t * 3 * plane + (size_t)Yo * OW + Xo;
            out[o]             = a0 * inv + m0;
            out[o + plane]     = a1 * inv + m1;
            out[o + 2 * plane] = a2 * inv + m2;
        }
        __syncthreads();   // stage boundary: protects ring-slot reuse
    }
}

// ---------------- launch ------------------------------------------------------
extern "C" void kernel_launch(void* const* d_in, const int* in_sizes, int n_in,
                              void* d_out, int out_size) {
    const float* noisy = (const float*)d_in[0];
    const float* deno  = (const float*)d_in[1];
    const float* pwts  = (const float*)d_in[2];
    float* out = (float*)d_out;

    cudaFuncSetAttribute(fold_kernel,
                         cudaFuncAttributeMaxDynamicSharedMemorySize,
                         SMEM_BYTES);

    dim3 mg(6, MEANS_CHUNKS);
    means_partial_kernel<<<mg, 512>>>(noisy);

    // fold with Programmatic Dependent Launch: starts while means_partial
    // still runs; dependency enforced in-kernel via griddepcontrol.wait.
    cudaLaunchAttribute attrs[1];
    attrs[0].id = cudaLaunchAttributeProgrammaticStreamSerialization;
    attrs[0].val.programmaticStreamSerializationAllowed = 1;

    cudaLaunchConfig_t cfg = {};
    cfg.gridDim  = dim3(NX, NSTRIPS, NT);   // 17 x 4 x 2 = 136 CTAs, one wave
    cfg.blockDim = dim3(TPB, 1, 1);
    cfg.dynamicSmemBytes = SMEM_BYTES;
    cfg.stream = 0;
    cfg.attrs = attrs;
    cfg.numAttrs = 1;

    cudaLaunchKernelEx(&cfg, fold_kernel, deno, pwts, out);
}